// round 14
// baseline (speedup 1.0000x reference)
#include <cuda_runtime.h>
#include <math.h>
#include <stdint.h>

#define NBINS 15

// ---------------- device-global scratch (allocation-free) ----------------
__device__ unsigned long long g_confq[NBINS];   // quantized conf sums (conf * 2^30)
__device__ unsigned int       g_cnt[NBINS];     // counts
__device__ unsigned int       g_acc[NBINS];     // accuracy counts
__device__ int                g_tgt64;          // 1 if target is int64, 0 if int32

// ---------------- kernel 0: zero accumulators + detect target dtype ------
__global__ void ece_zero_detect(const int* __restrict__ tgt_as_i32, int N) {
    int i = threadIdx.x;
    if (i < NBINS) { g_confq[i] = 0ull; g_cnt[i] = 0u; g_acc[i] = 0u; }
    if (i == 0) {
        // If the target buffer is int64 (little-endian, values in [0, C) >= 0),
        // every odd 32-bit word is zero. With int32 data these words are random
        // targets; P(first 128 odd words all zero) ~ (1/1000)^128 ~ 0.
        int n = N < 128 ? N : 128;
        int all_zero = 1;
        for (int k = 0; k < n; k++) {
            if (tgt_as_i32[2 * k + 1] != 0) { all_zero = 0; break; }
        }
        g_tgt64 = all_zero;
    }
}

// ---------------- kernel 1: per-row softmax-max + argmax + binning -------
// One warp per row. Each lane stages VPL float4 vectors in registers
// (front-batched LDG.128), pass1 = max/argmax, pass2 = sum of exp.
// Exactly one MUFU.EX2 per element -> stays HBM-bound.
template<int VPL>
__global__ __launch_bounds__(256)
void ece_main(const float* __restrict__ logits,
              const void*  __restrict__ target,
              int N, int C)
{
    const int NV   = C >> 2;                  // float4 per row
    const int lane = threadIdx.x & 31;
    const int warp = threadIdx.x >> 5;
    const int wpb  = blockDim.x >> 5;
    const int gwarp = blockIdx.x * wpb + warp;
    const int totalWarps = gridDim.x * wpb;

    __shared__ unsigned long long s_confq[NBINS];
    __shared__ unsigned int       s_cnt[NBINS];
    __shared__ unsigned int       s_acc[NBINS];
    if (threadIdx.x < NBINS) {
        s_confq[threadIdx.x] = 0ull; s_cnt[threadIdx.x] = 0u; s_acc[threadIdx.x] = 0u;
    }
    __syncthreads();

    const int is64 = g_tgt64;
    const long long* __restrict__ t64 = (const long long*)target;
    const int*       __restrict__ t32 = (const int*)target;

    for (int row = gwarp; row < N; row += totalWarps) {
        const float4* __restrict__ row4 =
            (const float4*)(logits + (size_t)row * (size_t)C);

        float4 buf[VPL];
        #pragma unroll
        for (int j = 0; j < VPL; j++) {
            int vi = lane + j * 32;
            if (vi < NV) buf[j] = __ldg(row4 + vi);
            else         buf[j] = make_float4(-INFINITY, -INFINITY, -INFINITY, -INFINITY);
        }

        // pass 1: lane-local max + first-occurrence argmax
        float m = -INFINITY; int idx = 0x7fffffff;
        #pragma unroll
        for (int j = 0; j < VPL; j++) {
            int base = 4 * (lane + j * 32);
            if (buf[j].x > m) { m = buf[j].x; idx = base;     }
            if (buf[j].y > m) { m = buf[j].y; idx = base + 1; }
            if (buf[j].z > m) { m = buf[j].z; idx = base + 2; }
            if (buf[j].w > m) { m = buf[j].w; idx = base + 3; }
        }
        float mm = (m == -INFINITY) ? 0.0f : m;   // safety for empty lanes

        // pass 2: sum of exp(l - m); padded -INF entries contribute exp(-inf)=0
        float s0 = 0.f, s1 = 0.f;
        #pragma unroll
        for (int j = 0; j < VPL; j++) {
            s0 += __expf(buf[j].x - mm);
            s1 += __expf(buf[j].y - mm);
            s0 += __expf(buf[j].z - mm);
            s1 += __expf(buf[j].w - mm);
        }
        float s = s0 + s1;

        // warp reduce (max, argmax, rescaled sum); lane 0 ends correct
        #pragma unroll
        for (int off = 16; off; off >>= 1) {
            float m2 = __shfl_down_sync(0xffffffffu, m,  off);
            float s2 = __shfl_down_sync(0xffffffffu, s,  off);
            int   i2 = __shfl_down_sync(0xffffffffu, idx, off);
            if (m2 > m) {
                s = s * __expf(m - m2) + s2; m = m2; idx = i2;
            } else if (m2 == m) {
                s += s2; if (i2 < idx) idx = i2;
            } else {
                s += s2 * __expf(m2 - m);
            }
        }

        if (lane == 0) {
            float conf = 1.0f / s;             // exp(m-m)/sum = max softmax prob
            int b = (int)ceilf(conf * (float)NBINS) - 1;
            b = min(max(b, 0), NBINS - 1);
            unsigned long long qc =
                (unsigned long long)__float2ull_rn(conf * 1073741824.0f); // *2^30
            atomicAdd(&s_confq[b], qc);
            atomicAdd(&s_cnt[b], 1u);
            long long tgt = is64 ? t64[row] : (long long)t32[row];
            if ((long long)idx == tgt) atomicAdd(&s_acc[b], 1u);
        }
    }

    __syncthreads();
    if (threadIdx.x < NBINS) {
        if (s_cnt[threadIdx.x]) {
            atomicAdd(&g_confq[threadIdx.x], s_confq[threadIdx.x]);
            atomicAdd(&g_cnt[threadIdx.x],   s_cnt[threadIdx.x]);
            atomicAdd(&g_acc[threadIdx.x],   s_acc[threadIdx.x]);
        }
    }
}

// ---------------- generic fallback (online softmax, scalar loads) --------
__global__ __launch_bounds__(256)
void ece_main_generic(const float* __restrict__ logits,
                      const void*  __restrict__ target,
                      int N, int C)
{
    const int lane = threadIdx.x & 31;
    const int warp = threadIdx.x >> 5;
    const int wpb  = blockDim.x >> 5;
    const int gwarp = blockIdx.x * wpb + warp;
    const int totalWarps = gridDim.x * wpb;

    __shared__ unsigned long long s_confq[NBINS];
    __shared__ unsigned int       s_cnt[NBINS];
    __shared__ unsigned int       s_acc[NBINS];
    if (threadIdx.x < NBINS) {
        s_confq[threadIdx.x] = 0ull; s_cnt[threadIdx.x] = 0u; s_acc[threadIdx.x] = 0u;
    }
    __syncthreads();

    const int is64 = g_tgt64;
    const long long* __restrict__ t64 = (const long long*)target;
    const int*       __restrict__ t32 = (const int*)target;

    for (int row = gwarp; row < N; row += totalWarps) {
        const float* __restrict__ r = logits + (size_t)row * (size_t)C;
        float m = -INFINITY, s = 0.f; int idx = 0x7fffffff;
        for (int c = lane; c < C; c += 32) {
            float v = __ldg(r + c);
            if (v > m) { s = s * __expf(m - v) + 1.0f; m = v; idx = c; }
            else       { s += __expf(v - m); }
        }
        #pragma unroll
        for (int off = 16; off; off >>= 1) {
            float m2 = __shfl_down_sync(0xffffffffu, m,  off);
            float s2 = __shfl_down_sync(0xffffffffu, s,  off);
            int   i2 = __shfl_down_sync(0xffffffffu, idx, off);
            if (m2 == -INFINITY) continue;
            if (m2 > m)       { s = s * __expf(m - m2) + s2; m = m2; idx = i2; }
            else if (m2 == m) { s += s2; if (i2 < idx) idx = i2; }
            else              { s += s2 * __expf(m2 - m); }
        }
        if (lane == 0) {
            float conf = 1.0f / s;
            int b = (int)ceilf(conf * (float)NBINS) - 1;
            b = min(max(b, 0), NBINS - 1);
            unsigned long long qc =
                (unsigned long long)__float2ull_rn(conf * 1073741824.0f);
            atomicAdd(&s_confq[b], qc);
            atomicAdd(&s_cnt[b], 1u);
            long long tgt = is64 ? t64[row] : (long long)t32[row];
            if ((long long)idx == tgt) atomicAdd(&s_acc[b], 1u);
        }
    }

    __syncthreads();
    if (threadIdx.x < NBINS) {
        if (s_cnt[threadIdx.x]) {
            atomicAdd(&g_confq[threadIdx.x], s_confq[threadIdx.x]);
            atomicAdd(&g_cnt[threadIdx.x],   s_cnt[threadIdx.x]);
            atomicAdd(&g_acc[threadIdx.x],   s_acc[threadIdx.x]);
        }
    }
}

// ---------------- kernel 2: finalize (ece, mean conf, mean acc) ----------
__global__ void ece_finalize(float* __restrict__ out, int out_size, int N)
{
    if (blockIdx.x == 0 && threadIdx.x == 0) {
        const double inv_q = 1.0 / 1073741824.0;
        double ece = 0.0, tot_conf = 0.0, tot_acc = 0.0;
        double invN = 1.0 / (double)N;
        for (int b = 0; b < NBINS; b++) {
            unsigned int cnt = g_cnt[b];
            double conf_sum = (double)g_confq[b] * inv_q;
            double acc_sum  = (double)g_acc[b];
            tot_conf += conf_sum;
            tot_acc  += acc_sum;
            if (cnt > 0) {
                double dc = (double)cnt;
                double avg_conf = conf_sum / dc;
                double avg_acc  = acc_sum / dc;
                double prop     = dc * invN;
                ece += (avg_conf - avg_acc) * prop;   // NO abs(), faithful to ref
            }
        }
        if (out_size > 0) out[0] = (float)ece;
        if (out_size > 1) out[1] = (float)(tot_conf * invN);
        if (out_size > 2) out[2] = (float)(tot_acc * invN);
        for (int i = 3; i < out_size; i++) out[i] = 0.0f;
    }
}

// ---------------- launch --------------------------------------------------
extern "C" void kernel_launch(void* const* d_in, const int* in_sizes, int n_in,
                              void* d_out, int out_size)
{
    const float* logits = (const float*)d_in[0];
    const void*  target = d_in[1];
    int N = in_sizes[1];
    int C = in_sizes[0] / N;

    ece_zero_detect<<<1, 32>>>((const int*)target, N);

    dim3 block(256);
    dim3 grid(1216);   // grid-stride; one warp per row

    int NV = C >> 2;
    if ((C & 3) == 0 && NV >= 32 && NV <= 256) {
        int vpl = (NV + 31) >> 5;
        switch (vpl) {
            case 1: ece_main<1><<<grid, block>>>(logits, target, N, C); break;
            case 2: ece_main<2><<<grid, block>>>(logits, target, N, C); break;
            case 3: ece_main<3><<<grid, block>>>(logits, target, N, C); break;
            case 4: ece_main<4><<<grid, block>>>(logits, target, N, C); break;
            case 5: ece_main<5><<<grid, block>>>(logits, target, N, C); break;
            case 6: ece_main<6><<<grid, block>>>(logits, target, N, C); break;
            case 7: ece_main<7><<<grid, block>>>(logits, target, N, C); break;
            default: ece_main<8><<<grid, block>>>(logits, target, N, C); break;
        }
    } else {
        ece_main_generic<<<grid, block>>>(logits, target, N, C);
    }

    ece_finalize<<<1, 32>>>((float*)d_out, out_size, N);
}

// round 15
// speedup vs baseline: 1.0005x; 1.0005x over previous
#include <cuda_runtime.h>
#include <math.h>
#include <stdint.h>

#define NBINS 15

// ---------------- device-global scratch (allocation-free) ----------------
__device__ unsigned long long g_confq[NBINS];   // quantized conf sums (conf * 2^30)
__device__ unsigned int       g_cnt[NBINS];     // counts
__device__ unsigned int       g_acc[NBINS];     // accuracy counts
__device__ int                g_tgt64;          // 1 if target is int64, 0 if int32

// ---------------- kernel 0: zero accumulators + detect target dtype ------
__global__ void ece_zero_detect(const int* __restrict__ tgt_as_i32, int N) {
    int i = threadIdx.x;
    if (i < NBINS) { g_confq[i] = 0ull; g_cnt[i] = 0u; g_acc[i] = 0u; }
    if (i == 0) {
        // If the target buffer is int64 (little-endian, values in [0, C) >= 0),
        // every odd 32-bit word is zero. With int32 data these words are random
        // targets; P(first 128 odd words all zero) ~ (1/1000)^128 ~ 0.
        int n = N < 128 ? N : 128;
        int all_zero = 1;
        for (int k = 0; k < n; k++) {
            if (tgt_as_i32[2 * k + 1] != 0) { all_zero = 0; break; }
        }
        g_tgt64 = all_zero;
    }
}

// ---------------- kernel 1: per-row softmax-max + argmax + binning -------
// One warp per row. Each lane stages VPL float4 vectors in registers
// (front-batched LDG.128), pass1 = max/argmax, pass2 = sum of exp.
// Exactly one MUFU.EX2 per element -> stays HBM-bound.
template<int VPL>
__global__ __launch_bounds__(256)
void ece_main(const float* __restrict__ logits,
              const void*  __restrict__ target,
              int N, int C)
{
    const int NV   = C >> 2;                  // float4 per row
    const int lane = threadIdx.x & 31;
    const int warp = threadIdx.x >> 5;
    const int wpb  = blockDim.x >> 5;
    const int gwarp = blockIdx.x * wpb + warp;
    const int totalWarps = gridDim.x * wpb;

    __shared__ unsigned long long s_confq[NBINS];
    __shared__ unsigned int       s_cnt[NBINS];
    __shared__ unsigned int       s_acc[NBINS];
    if (threadIdx.x < NBINS) {
        s_confq[threadIdx.x] = 0ull; s_cnt[threadIdx.x] = 0u; s_acc[threadIdx.x] = 0u;
    }
    __syncthreads();

    const int is64 = g_tgt64;
    const long long* __restrict__ t64 = (const long long*)target;
    const int*       __restrict__ t32 = (const int*)target;

    for (int row = gwarp; row < N; row += totalWarps) {
        const float4* __restrict__ row4 =
            (const float4*)(logits + (size_t)row * (size_t)C);

        float4 buf[VPL];
        #pragma unroll
        for (int j = 0; j < VPL; j++) {
            int vi = lane + j * 32;
            if (vi < NV) buf[j] = __ldg(row4 + vi);
            else         buf[j] = make_float4(-INFINITY, -INFINITY, -INFINITY, -INFINITY);
        }

        // pass 1: lane-local max + first-occurrence argmax
        float m = -INFINITY; int idx = 0x7fffffff;
        #pragma unroll
        for (int j = 0; j < VPL; j++) {
            int base = 4 * (lane + j * 32);
            if (buf[j].x > m) { m = buf[j].x; idx = base;     }
            if (buf[j].y > m) { m = buf[j].y; idx = base + 1; }
            if (buf[j].z > m) { m = buf[j].z; idx = base + 2; }
            if (buf[j].w > m) { m = buf[j].w; idx = base + 3; }
        }
        float mm = (m == -INFINITY) ? 0.0f : m;   // safety for empty lanes

        // pass 2: sum of exp(l - m); padded -INF entries contribute exp(-inf)=0
        float s0 = 0.f, s1 = 0.f;
        #pragma unroll
        for (int j = 0; j < VPL; j++) {
            s0 += __expf(buf[j].x - mm);
            s1 += __expf(buf[j].y - mm);
            s0 += __expf(buf[j].z - mm);
            s1 += __expf(buf[j].w - mm);
        }
        float s = s0 + s1;

        // warp reduce (max, argmax, rescaled sum); lane 0 ends correct
        #pragma unroll
        for (int off = 16; off; off >>= 1) {
            float m2 = __shfl_down_sync(0xffffffffu, m,  off);
            float s2 = __shfl_down_sync(0xffffffffu, s,  off);
            int   i2 = __shfl_down_sync(0xffffffffu, idx, off);
            if (m2 > m) {
                s = s * __expf(m - m2) + s2; m = m2; idx = i2;
            } else if (m2 == m) {
                s += s2; if (i2 < idx) idx = i2;
            } else {
                s += s2 * __expf(m2 - m);
            }
        }

        if (lane == 0) {
            float conf = 1.0f / s;             // exp(m-m)/sum = max softmax prob
            int b = (int)ceilf(conf * (float)NBINS) - 1;
            b = min(max(b, 0), NBINS - 1);
            unsigned long long qc =
                (unsigned long long)__float2ull_rn(conf * 1073741824.0f); // *2^30
            atomicAdd(&s_confq[b], qc);
            atomicAdd(&s_cnt[b], 1u);
            long long tgt = is64 ? t64[row] : (long long)t32[row];
            if ((long long)idx == tgt) atomicAdd(&s_acc[b], 1u);
        }
    }

    __syncthreads();
    if (threadIdx.x < NBINS) {
        if (s_cnt[threadIdx.x]) {
            atomicAdd(&g_confq[threadIdx.x], s_confq[threadIdx.x]);
            atomicAdd(&g_cnt[threadIdx.x],   s_cnt[threadIdx.x]);
            atomicAdd(&g_acc[threadIdx.x],   s_acc[threadIdx.x]);
        }
    }
}

// ---------------- generic fallback (online softmax, scalar loads) --------
__global__ __launch_bounds__(256)
void ece_main_generic(const float* __restrict__ logits,
                      const void*  __restrict__ target,
                      int N, int C)
{
    const int lane = threadIdx.x & 31;
    const int warp = threadIdx.x >> 5;
    const int wpb  = blockDim.x >> 5;
    const int gwarp = blockIdx.x * wpb + warp;
    const int totalWarps = gridDim.x * wpb;

    __shared__ unsigned long long s_confq[NBINS];
    __shared__ unsigned int       s_cnt[NBINS];
    __shared__ unsigned int       s_acc[NBINS];
    if (threadIdx.x < NBINS) {
        s_confq[threadIdx.x] = 0ull; s_cnt[threadIdx.x] = 0u; s_acc[threadIdx.x] = 0u;
    }
    __syncthreads();

    const int is64 = g_tgt64;
    const long long* __restrict__ t64 = (const long long*)target;
    const int*       __restrict__ t32 = (const int*)target;

    for (int row = gwarp; row < N; row += totalWarps) {
        const float* __restrict__ r = logits + (size_t)row * (size_t)C;
        float m = -INFINITY, s = 0.f; int idx = 0x7fffffff;
        for (int c = lane; c < C; c += 32) {
            float v = __ldg(r + c);
            if (v > m) { s = s * __expf(m - v) + 1.0f; m = v; idx = c; }
            else       { s += __expf(v - m); }
        }
        #pragma unroll
        for (int off = 16; off; off >>= 1) {
            float m2 = __shfl_down_sync(0xffffffffu, m,  off);
            float s2 = __shfl_down_sync(0xffffffffu, s,  off);
            int   i2 = __shfl_down_sync(0xffffffffu, idx, off);
            if (m2 == -INFINITY) continue;
            if (m2 > m)       { s = s * __expf(m - m2) + s2; m = m2; idx = i2; }
            else if (m2 == m) { s += s2; if (i2 < idx) idx = i2; }
            else              { s += s2 * __expf(m2 - m); }
        }
        if (lane == 0) {
            float conf = 1.0f / s;
            int b = (int)ceilf(conf * (float)NBINS) - 1;
            b = min(max(b, 0), NBINS - 1);
            unsigned long long qc =
                (unsigned long long)__float2ull_rn(conf * 1073741824.0f);
            atomicAdd(&s_confq[b], qc);
            atomicAdd(&s_cnt[b], 1u);
            long long tgt = is64 ? t64[row] : (long long)t32[row];
            if ((long long)idx == tgt) atomicAdd(&s_acc[b], 1u);
        }
    }

    __syncthreads();
    if (threadIdx.x < NBINS) {
        if (s_cnt[threadIdx.x]) {
            atomicAdd(&g_confq[threadIdx.x], s_confq[threadIdx.x]);
            atomicAdd(&g_cnt[threadIdx.x],   s_cnt[threadIdx.x]);
            atomicAdd(&g_acc[threadIdx.x],   s_acc[threadIdx.x]);
        }
    }
}

// ---------------- kernel 2: finalize (ece, mean conf, mean acc) ----------
__global__ void ece_finalize(float* __restrict__ out, int out_size, int N)
{
    if (blockIdx.x == 0 && threadIdx.x == 0) {
        const double inv_q = 1.0 / 1073741824.0;
        double ece = 0.0, tot_conf = 0.0, tot_acc = 0.0;
        double invN = 1.0 / (double)N;
        for (int b = 0; b < NBINS; b++) {
            unsigned int cnt = g_cnt[b];
            double conf_sum = (double)g_confq[b] * inv_q;
            double acc_sum  = (double)g_acc[b];
            tot_conf += conf_sum;
            tot_acc  += acc_sum;
            if (cnt > 0) {
                double dc = (double)cnt;
                double avg_conf = conf_sum / dc;
                double avg_acc  = acc_sum / dc;
                double prop     = dc * invN;
                ece += (avg_conf - avg_acc) * prop;   // NO abs(), faithful to ref
            }
        }
        if (out_size > 0) out[0] = (float)ece;
        if (out_size > 1) out[1] = (float)(tot_conf * invN);
        if (out_size > 2) out[2] = (float)(tot_acc * invN);
        for (int i = 3; i < out_size; i++) out[i] = 0.0f;
    }
}

// ---------------- launch --------------------------------------------------
extern "C" void kernel_launch(void* const* d_in, const int* in_sizes, int n_in,
                              void* d_out, int out_size)
{
    const float* logits = (const float*)d_in[0];
    const void*  target = d_in[1];
    int N = in_sizes[1];
    int C = in_sizes[0] / N;

    ece_zero_detect<<<1, 32>>>((const int*)target, N);

    dim3 block(256);
    dim3 grid(1216);   // grid-stride; one warp per row

    int NV = C >> 2;
    if ((C & 3) == 0 && NV >= 32 && NV <= 256) {
        int vpl = (NV + 31) >> 5;
        switch (vpl) {
            case 1: ece_main<1><<<grid, block>>>(logits, target, N, C); break;
            case 2: ece_main<2><<<grid, block>>>(logits, target, N, C); break;
            case 3: ece_main<3><<<grid, block>>>(logits, target, N, C); break;
            case 4: ece_main<4><<<grid, block>>>(logits, target, N, C); break;
            case 5: ece_main<5><<<grid, block>>>(logits, target, N, C); break;
            case 6: ece_main<6><<<grid, block>>>(logits, target, N, C); break;
            case 7: ece_main<7><<<grid, block>>>(logits, target, N, C); break;
            default: ece_main<8><<<grid, block>>>(logits, target, N, C); break;
        }
    } else {
        ece_main_generic<<<grid, block>>>(logits, target, N, C);
    }

    ece_finalize<<<1, 32>>>((float*)d_out, out_size, N);
}

// round 16
// speedup vs baseline: 1.1096x; 1.1090x over previous
#include <cuda_runtime.h>
#include <math.h>
#include <stdint.h>

#define NBINS 15
#define L2E 1.4426950408889634f

// ---------------- device-global scratch (allocation-free) ----------------
__device__ unsigned long long g_confq[NBINS];   // quantized conf sums (conf * 2^30)
__device__ unsigned int       g_cnt[NBINS];     // counts
__device__ unsigned int       g_acc[NBINS];     // accuracy counts
__device__ int                g_tgt64;          // 1 if target is int64, 0 if int32

__device__ __forceinline__ float ex2f(float x) {
    float y; asm("ex2.approx.f32 %0, %1;" : "=f"(y) : "f"(x)); return y;
}

// ---------------- kernel 0: zero accumulators + detect target dtype ------
// Parallel detection: int64 targets (>=0, < C) have all-zero odd 32-bit words.
__global__ void ece_init(const int* __restrict__ tgt_as_i32, int N) {
    int i = threadIdx.x;
    if (i < NBINS) { g_confq[i] = 0ull; g_cnt[i] = 0u; g_acc[i] = 0u; }
    __shared__ int flag;
    if (i == 0) flag = 1;
    __syncthreads();
    int n = N >> 1; if (n > 128) n = 128;   // safe for int32 buffers too
    if (i < n && tgt_as_i32[2 * i + 1] != 0) flag = 0;
    __syncthreads();
    if (i == 0) g_tgt64 = flag;
}

// ---------------- kernel 1: TMA-pipelined softmax-max + argmax + binning --
// 4 warps/block, one row per warp per iteration, 2-stage smem ring per warp
// fed by cp.async.bulk (1D TMA). Compute stages row into 32 regs, does
// max/argmax pass then exp-sum pass (exactly 1 MUFU.EX2 per element).
__global__ __launch_bounds__(128, 6)
void ece_main_tma(const float* __restrict__ logits,
                  const void*  __restrict__ target,
                  int N, int C)
{
    const int NV = C >> 2;                     // float4 per row (<= 256)
    const unsigned bytes = (unsigned)C * 4u;   // row bytes (mult of 16)
    const int lane = threadIdx.x & 31;
    const int wid  = threadIdx.x >> 5;         // 0..3
    const int gwarp  = blockIdx.x * 4 + wid;
    const int stride = gridDim.x * 4;

    __shared__ __align__(16) float4 stg[4][2][256];   // 32 KB: 4 warps x 2 stages
    __shared__ unsigned long long   mb[4][2];
    __shared__ unsigned long long   s_confq[NBINS];
    __shared__ unsigned int         s_cnt[NBINS];
    __shared__ unsigned int         s_acc[NBINS];

    if (threadIdx.x < NBINS) {
        s_confq[threadIdx.x] = 0ull; s_cnt[threadIdx.x] = 0u; s_acc[threadIdx.x] = 0u;
    }

    uint32_t mbar[2], sbase[2];
    mbar[0]  = (uint32_t)__cvta_generic_to_shared(&mb[wid][0]);
    mbar[1]  = (uint32_t)__cvta_generic_to_shared(&mb[wid][1]);
    sbase[0] = (uint32_t)__cvta_generic_to_shared(&stg[wid][0][0]);
    sbase[1] = (uint32_t)__cvta_generic_to_shared(&stg[wid][1][0]);

    if (lane == 0) {
        asm volatile("mbarrier.init.shared.b64 [%0], 1;" :: "r"(mbar[0]) : "memory");
        asm volatile("mbarrier.init.shared.b64 [%0], 1;" :: "r"(mbar[1]) : "memory");
    }
    asm volatile("fence.proxy.async.shared::cta;" ::: "memory");
    __syncthreads();

    const int is64 = g_tgt64;
    const long long* __restrict__ t64 = (const long long*)target;
    const int*       __restrict__ t32 = (const int*)target;

    // prologue: fill both stages
    if (lane == 0) {
        #pragma unroll
        for (int s = 0; s < 2; s++) {
            long long r = (long long)gwarp + (long long)s * stride;
            if (r < (long long)N) {
                asm volatile("mbarrier.arrive.expect_tx.shared.b64 _, [%0], %1;"
                             :: "r"(mbar[s]), "r"(bytes) : "memory");
                const float* src = logits + r * (long long)C;
                asm volatile(
                    "cp.async.bulk.shared::cluster.global.mbarrier::complete_tx::bytes "
                    "[%0], [%1], %2, [%3];"
                    :: "r"(sbase[s]), "l"(src), "r"(bytes), "r"(mbar[s]) : "memory");
            }
        }
    }

    int it = 0;
    for (long long row = gwarp; row < (long long)N; row += stride, it++) {
        const int s = it & 1;
        const unsigned ph = (unsigned)((it >> 1) & 1);

        // wait for stage full (acquire)
        asm volatile(
            "{\n\t.reg .pred P;\n"
            "WLP%=:\n\tmbarrier.try_wait.parity.acquire.cta.shared::cta.b64 P, [%0], %1, 0x989680;\n"
            "\t@P bra WDN%=;\n\tbra WLP%=;\n"
            "WDN%=:\n\t}"
            :: "r"(mbar[s]), "r"(ph) : "memory");

        // stage row into registers
        const float4* __restrict__ sp = &stg[wid][s][0];
        float4 buf[8];
        #pragma unroll
        for (int j = 0; j < 8; j++) {
            int vi = lane + j * 32;
            if (vi < NV) buf[j] = sp[vi];
            else         buf[j] = make_float4(-INFINITY, -INFINITY, -INFINITY, -INFINITY);
        }

        // refill this stage immediately (overlaps TMA with compute below;
        // TMA write arrives >>600cyc later, LDS above completes in ~30cyc)
        {
            long long nr = row + 2LL * stride;
            if (lane == 0 && nr < (long long)N) {
                asm volatile("mbarrier.arrive.expect_tx.shared.b64 _, [%0], %1;"
                             :: "r"(mbar[s]), "r"(bytes) : "memory");
                const float* src = logits + nr * (long long)C;
                asm volatile(
                    "cp.async.bulk.shared::cluster.global.mbarrier::complete_tx::bytes "
                    "[%0], [%1], %2, [%3];"
                    :: "r"(sbase[s]), "l"(src), "r"(bytes), "r"(mbar[s]) : "memory");
            }
        }

        // pass 1: lane-local max + first-occurrence argmax
        float m = -INFINITY; int idx = 0x7fffffff;
        #pragma unroll
        for (int j = 0; j < 8; j++) {
            int base = 4 * (lane + j * 32);
            if (buf[j].x > m) { m = buf[j].x; idx = base;     }
            if (buf[j].y > m) { m = buf[j].y; idx = base + 1; }
            if (buf[j].z > m) { m = buf[j].z; idx = base + 2; }
            if (buf[j].w > m) { m = buf[j].w; idx = base + 3; }
        }

        // pass 2: sum exp(v - m) = ex2(v*L2E - m*L2E); 1 FFMA + 1 MUFU / elem
        float nb = -m * L2E;   // m finite: every lane has >=7 valid elements
        float s0 = 0.f, s1 = 0.f, s2 = 0.f, s3 = 0.f;
        #pragma unroll
        for (int j = 0; j < 8; j++) {
            s0 += ex2f(fmaf(buf[j].x, L2E, nb));
            s1 += ex2f(fmaf(buf[j].y, L2E, nb));
            s2 += ex2f(fmaf(buf[j].z, L2E, nb));
            s3 += ex2f(fmaf(buf[j].w, L2E, nb));
        }
        float ssum = (s0 + s1) + (s2 + s3);

        // warp reduce (max, argmax, rescaled sum)
        #pragma unroll
        for (int off = 16; off; off >>= 1) {
            float m2 = __shfl_down_sync(0xffffffffu, m,    off);
            float sx = __shfl_down_sync(0xffffffffu, ssum, off);
            int   i2 = __shfl_down_sync(0xffffffffu, idx,  off);
            if (m2 > m) {
                ssum = ssum * ex2f((m - m2) * L2E) + sx; m = m2; idx = i2;
            } else if (m2 == m) {
                ssum += sx; if (i2 < idx) idx = i2;
            } else {
                ssum += sx * ex2f((m2 - m) * L2E);
            }
        }

        if (lane == 0) {
            float conf = 1.0f / ssum;
            int b = (int)ceilf(conf * (float)NBINS) - 1;
            b = min(max(b, 0), NBINS - 1);
            unsigned long long qc =
                (unsigned long long)__float2ull_rn(conf * 1073741824.0f); // *2^30
            atomicAdd(&s_confq[b], qc);
            atomicAdd(&s_cnt[b], 1u);
            long long tgt = is64 ? t64[row] : (long long)t32[row];
            if ((long long)idx == tgt) atomicAdd(&s_acc[b], 1u);
        }
    }

    __syncthreads();
    if (threadIdx.x < NBINS) {
        if (s_cnt[threadIdx.x]) {
            atomicAdd(&g_confq[threadIdx.x], s_confq[threadIdx.x]);
            atomicAdd(&g_cnt[threadIdx.x],   s_cnt[threadIdx.x]);
            atomicAdd(&g_acc[threadIdx.x],   s_acc[threadIdx.x]);
        }
    }
}

// ---------------- generic fallback (online softmax, scalar loads) --------
__global__ __launch_bounds__(256)
void ece_main_generic(const float* __restrict__ logits,
                      const void*  __restrict__ target,
                      int N, int C)
{
    const int lane = threadIdx.x & 31;
    const int warp = threadIdx.x >> 5;
    const int wpb  = blockDim.x >> 5;
    const int gwarp = blockIdx.x * wpb + warp;
    const int totalWarps = gridDim.x * wpb;

    __shared__ unsigned long long s_confq[NBINS];
    __shared__ unsigned int       s_cnt[NBINS];
    __shared__ unsigned int       s_acc[NBINS];
    if (threadIdx.x < NBINS) {
        s_confq[threadIdx.x] = 0ull; s_cnt[threadIdx.x] = 0u; s_acc[threadIdx.x] = 0u;
    }
    __syncthreads();

    const int is64 = g_tgt64;
    const long long* __restrict__ t64 = (const long long*)target;
    const int*       __restrict__ t32 = (const int*)target;

    for (int row = gwarp; row < N; row += totalWarps) {
        const float* __restrict__ r = logits + (size_t)row * (size_t)C;
        float m = -INFINITY, s = 0.f; int idx = 0x7fffffff;
        for (int c = lane; c < C; c += 32) {
            float v = __ldg(r + c);
            if (v > m) { s = s * __expf(m - v) + 1.0f; m = v; idx = c; }
            else       { s += __expf(v - m); }
        }
        #pragma unroll
        for (int off = 16; off; off >>= 1) {
            float m2 = __shfl_down_sync(0xffffffffu, m,  off);
            float s2 = __shfl_down_sync(0xffffffffu, s,  off);
            int   i2 = __shfl_down_sync(0xffffffffu, idx, off);
            if (m2 == -INFINITY) continue;
            if (m2 > m)       { s = s * __expf(m - m2) + s2; m = m2; idx = i2; }
            else if (m2 == m) { s += s2; if (i2 < idx) idx = i2; }
            else              { s += s2 * __expf(m2 - m); }
        }
        if (lane == 0) {
            float conf = 1.0f / s;
            int b = (int)ceilf(conf * (float)NBINS) - 1;
            b = min(max(b, 0), NBINS - 1);
            unsigned long long qc =
                (unsigned long long)__float2ull_rn(conf * 1073741824.0f);
            atomicAdd(&s_confq[b], qc);
            atomicAdd(&s_cnt[b], 1u);
            long long tgt = is64 ? t64[row] : (long long)t32[row];
            if ((long long)idx == tgt) atomicAdd(&s_acc[b], 1u);
        }
    }

    __syncthreads();
    if (threadIdx.x < NBINS) {
        if (s_cnt[threadIdx.x]) {
            atomicAdd(&g_confq[threadIdx.x], s_confq[threadIdx.x]);
            atomicAdd(&g_cnt[threadIdx.x],   s_cnt[threadIdx.x]);
            atomicAdd(&g_acc[threadIdx.x],   s_acc[threadIdx.x]);
        }
    }
}

// ---------------- kernel 2: finalize (ece, mean conf, mean acc) ----------
__global__ void ece_finalize(float* __restrict__ out, int out_size, int N)
{
    if (blockIdx.x == 0 && threadIdx.x == 0) {
        const double inv_q = 1.0 / 1073741824.0;
        double ece = 0.0, tot_conf = 0.0, tot_acc = 0.0;
        double invN = 1.0 / (double)N;
        for (int b = 0; b < NBINS; b++) {
            unsigned int cnt = g_cnt[b];
            double conf_sum = (double)g_confq[b] * inv_q;
            double acc_sum  = (double)g_acc[b];
            tot_conf += conf_sum;
            tot_acc  += acc_sum;
            if (cnt > 0) {
                double dc = (double)cnt;
                double avg_conf = conf_sum / dc;
                double avg_acc  = acc_sum / dc;
                double prop     = dc * invN;
                ece += (avg_conf - avg_acc) * prop;   // NO abs(), faithful to ref
            }
        }
        if (out_size > 0) out[0] = (float)ece;
        if (out_size > 1) out[1] = (float)(tot_conf * invN);
        if (out_size > 2) out[2] = (float)(tot_acc * invN);
        for (int i = 3; i < out_size; i++) out[i] = 0.0f;
    }
}

// ---------------- launch --------------------------------------------------
extern "C" void kernel_launch(void* const* d_in, const int* in_sizes, int n_in,
                              void* d_out, int out_size)
{
    const float* logits = (const float*)d_in[0];
    const void*  target = d_in[1];
    int N = in_sizes[1];
    int C = in_sizes[0] / N;

    ece_init<<<1, 128>>>((const int*)target, N);

    int NV = C >> 2;
    if ((C & 3) == 0 && NV >= 32 && NV <= 256) {
        // 152 SMs x 6 blocks = one full wave of persistent blocks
        ece_main_tma<<<912, 128>>>(logits, target, N, C);
    } else {
        ece_main_generic<<<1216, 256>>>(logits, target, N, C);
    }

    ece_finalize<<<1, 32>>>((float*)d_out, out_size, N);
}